// round 1
// baseline (speedup 1.0000x reference)
#include <cuda_runtime.h>

// Fused CBF-QP controller: one thread per (b,t) row.
// Per row: 2x tanh-MLP [16->128], analytic grad, f/g bilinear forms, KKT epilogue.
// All weights broadcast from shared memory (pre-transposed for float4 reads).

namespace {

constexpr int S_DIM = 16;
constexpr int H_DIM = 128;
constexpr int A_DIM = 4;
constexpr float QP_EPS = 1e-8f;

// Accurate fast tanh: tanh(x) = 1 - 2/(1+exp(2x)), exp via MUFU.EX2, rcp via MUFU.RCP.
// Error ~1e-6 (vs ~6e-4 for tanh.approx) — safe under the 1e-3 harness threshold.
__device__ __forceinline__ float fast_tanh(float x) {
    float z = fminf(fmaxf(x, -15.0f), 15.0f);   // tanh saturates to +-1.0f beyond this
    float e;
    asm("ex2.approx.f32 %0, %1;" : "=f"(e) : "f"(z * 2.885390081777927f)); // 2*log2(e)
    float r;
    asm("rcp.approx.f32 %0, %1;" : "=f"(r) : "f"(e + 1.0f));
    return fmaf(-2.0f, r, 1.0f);
}

// dot(s[0:16], w) + acc, two chains for ILP
__device__ __forceinline__ float dot16(const float* s,
                                       float4 w0, float4 w1, float4 w2, float4 w3,
                                       float acc) {
    float a0 = acc, a1 = 0.0f;
    a0 = fmaf(s[0],  w0.x, a0); a1 = fmaf(s[8],  w2.x, a1);
    a0 = fmaf(s[1],  w0.y, a0); a1 = fmaf(s[9],  w2.y, a1);
    a0 = fmaf(s[2],  w0.z, a0); a1 = fmaf(s[10], w2.z, a1);
    a0 = fmaf(s[3],  w0.w, a0); a1 = fmaf(s[11], w2.w, a1);
    a0 = fmaf(s[4],  w1.x, a0); a1 = fmaf(s[12], w3.x, a1);
    a0 = fmaf(s[5],  w1.y, a0); a1 = fmaf(s[13], w3.y, a1);
    a0 = fmaf(s[6],  w1.z, a0); a1 = fmaf(s[14], w3.z, a1);
    a0 = fmaf(s[7],  w1.w, a0); a1 = fmaf(s[15], w3.w, a1);
    return a0 + a1;
}

__global__ void __launch_bounds__(256)
cbf_fused(const float* __restrict__ state,
          const float* __restrict__ Wc1, const float* __restrict__ bc1,
          const float* __restrict__ Wc2, const float* __restrict__ bc2,
          const float* __restrict__ Wh1, const float* __restrict__ bh1,
          const float* __restrict__ wh2, const float* __restrict__ bh2,
          const float* __restrict__ Wf,  const float* __restrict__ bf,
          const float* __restrict__ Wg,  const float* __restrict__ bg,
          float* __restrict__ out, int total)
{
    // Shared weight staging (~26 KB).
    __shared__ float4 sWc1[H_DIM][4];        // Wc1^T: [j][k/4], Wc1T[j][k] = Wc1[k*H + j]
    __shared__ float4 sWh1[H_DIM][4];        // Wh1^T
    __shared__ float4 sWc2[H_DIM];           // Wc2 rows (already [H][4])
    __shared__ float4 sB[H_DIM];             // packed (bc1[j], bh1[j], wh2[j], 0)
    __shared__ float4 sWf[S_DIM][4];         // Wf^T: [s'][k/4]
    __shared__ float4 sWg[S_DIM][S_DIM];     // [k][s'] -> float4 over a (native Wg layout)
    __shared__ float4 sbg[S_DIM];            // bg as [s'][a]
    __shared__ float  sbf[S_DIM];
    __shared__ float  sbc2[A_DIM];
    __shared__ float  sbh2;

    const int tid = threadIdx.x;

    for (int idx = tid; idx < H_DIM * S_DIM; idx += blockDim.x) {
        const int j = idx >> 4, k = idx & 15;
        reinterpret_cast<float*>(sWc1)[idx] = Wc1[k * H_DIM + j];
        reinterpret_cast<float*>(sWh1)[idx] = Wh1[k * H_DIM + j];
    }
    for (int j = tid; j < H_DIM; j += blockDim.x) {
        sWc2[j] = reinterpret_cast<const float4*>(Wc2)[j];
        sB[j]   = make_float4(bc1[j], bh1[j], wh2[j], 0.0f);
    }
    for (int idx = tid; idx < S_DIM * S_DIM; idx += blockDim.x) {
        const int sp = idx >> 4, k = idx & 15;
        reinterpret_cast<float*>(sWf)[idx] = Wf[k * S_DIM + sp];
        reinterpret_cast<float4*>(sWg)[idx] = reinterpret_cast<const float4*>(Wg)[idx];
    }
    if (tid < S_DIM) { sbf[tid] = bf[tid]; sbg[tid] = reinterpret_cast<const float4*>(bg)[tid]; }
    if (tid < A_DIM) sbc2[tid] = bc2[tid];
    if (tid == 0)    sbh2 = bh2[0];
    __syncthreads();

    const int row = blockIdx.x * blockDim.x + tid;
    if (row >= total) return;

    // Load this row's state into registers.
    float s[16];
    {
        const float4* sp4 = reinterpret_cast<const float4*>(state) + (size_t)row * 4;
        float4 a = sp4[0], b = sp4[1], c = sp4[2], d = sp4[3];
        s[0]=a.x;  s[1]=a.y;  s[2]=a.z;  s[3]=a.w;
        s[4]=b.x;  s[5]=b.y;  s[6]=b.z;  s[7]=b.w;
        s[8]=c.x;  s[9]=c.y;  s[10]=c.z; s[11]=c.w;
        s[12]=d.x; s[13]=d.y; s[14]=d.z; s[15]=d.w;
    }

    float uu0 = 0.f, uu1 = 0.f, uu2 = 0.f, uu3 = 0.f;  // tanh(sWc1)@Wc2 accumulators
    float hval = 0.f;
    float dh[16];
    #pragma unroll
    for (int k = 0; k < 16; ++k) dh[k] = 0.f;

    // Main H-loop: both MLP branches fused, Wh1 column reused for grad accumulation.
    #pragma unroll 4
    for (int j = 0; j < H_DIM; ++j) {
        const float4 bias = sB[j];

        // controller branch
        const float4 wa = sWc1[j][0], wb = sWc1[j][1], wc = sWc1[j][2], wd = sWc1[j][3];
        const float t1 = fast_tanh(dot16(s, wa, wb, wc, wd, bias.x));
        const float4 w2 = sWc2[j];
        uu0 = fmaf(t1, w2.x, uu0); uu1 = fmaf(t1, w2.y, uu1);
        uu2 = fmaf(t1, w2.z, uu2); uu3 = fmaf(t1, w2.w, uu3);

        // CBF branch
        const float4 ha = sWh1[j][0], hb = sWh1[j][1], hc = sWh1[j][2], hd = sWh1[j][3];
        const float t2 = fast_tanh(dot16(s, ha, hb, hc, hd, bias.y));
        hval = fmaf(t2, bias.z, hval);
        const float cj = fmaf(-t2 * t2, bias.z, bias.z);   // (1 - t2^2) * wh2[j]
        dh[0]  = fmaf(cj, ha.x, dh[0]);  dh[1]  = fmaf(cj, ha.y, dh[1]);
        dh[2]  = fmaf(cj, ha.z, dh[2]);  dh[3]  = fmaf(cj, ha.w, dh[3]);
        dh[4]  = fmaf(cj, hb.x, dh[4]);  dh[5]  = fmaf(cj, hb.y, dh[5]);
        dh[6]  = fmaf(cj, hb.z, dh[6]);  dh[7]  = fmaf(cj, hb.w, dh[7]);
        dh[8]  = fmaf(cj, hc.x, dh[8]);  dh[9]  = fmaf(cj, hc.y, dh[9]);
        dh[10] = fmaf(cj, hc.z, dh[10]); dh[11] = fmaf(cj, hc.w, dh[11]);
        dh[12] = fmaf(cj, hd.x, dh[12]); dh[13] = fmaf(cj, hd.y, dh[13]);
        dh[14] = fmaf(cj, hd.z, dh[14]); dh[15] = fmaf(cj, hd.w, dh[15]);
    }

    // right = h + dh . f,  f = state@Wf + bf
    float right = hval + sbh2;
    #pragma unroll
    for (int sp = 0; sp < S_DIM; ++sp) {
        const float fv = dot16(s, sWf[sp][0], sWf[sp][1], sWf[sp][2], sWf[sp][3], sbf[sp]);
        right = fmaf(dh[sp], fv, right);
    }

    // left[a] = -sum_s' dh[s'] * g[s'][a],  g = (state@Wg + bg)
    float l0 = 0.f, l1 = 0.f, l2 = 0.f, l3 = 0.f;
    #pragma unroll
    for (int sp = 0; sp < S_DIM; ++sp) {
        float4 acc = sbg[sp];
        #pragma unroll
        for (int k = 0; k < S_DIM; ++k) {
            const float4 wg = sWg[k][sp];
            acc.x = fmaf(s[k], wg.x, acc.x);
            acc.y = fmaf(s[k], wg.y, acc.y);
            acc.z = fmaf(s[k], wg.z, acc.z);
            acc.w = fmaf(s[k], wg.w, acc.w);
        }
        const float ndh = -dh[sp];
        l0 = fmaf(ndh, acc.x, l0);
        l1 = fmaf(ndh, acc.y, l1);
        l2 = fmaf(ndh, acc.z, l2);
        l3 = fmaf(ndh, acc.w, l3);
    }

    // QP epilogue: u_unc = -u_ref = 2*(t1@Wc2 + bc2)
    const float u0 = 2.0f * (uu0 + sbc2[0]);
    const float u1 = 2.0f * (uu1 + sbc2[1]);
    const float u2 = 2.0f * (uu2 + sbc2[2]);
    const float u3 = 2.0f * (uu3 + sbc2[3]);

    const float viol = l0*u0 + l1*u1 + l2*u2 + l3*u3 - right;
    const float den  = l0*l0 + l1*l1 + l2*l2 + l3*l3 + QP_EPS;
    const float lam  = viol > 0.0f ? (viol / den) : 0.0f;

    float4 res;
    res.x = fmaf(-lam, l0, u0);
    res.y = fmaf(-lam, l1, u1);
    res.z = fmaf(-lam, l2, u2);
    res.w = fmaf(-lam, l3, u3);
    reinterpret_cast<float4*>(out)[row] = res;
}

} // namespace

extern "C" void kernel_launch(void* const* d_in, const int* in_sizes, int n_in,
                              void* d_out, int out_size) {
    const float* state = (const float*)d_in[0];
    const float* Wc1   = (const float*)d_in[1];
    const float* bc1   = (const float*)d_in[2];
    const float* Wc2   = (const float*)d_in[3];
    const float* bc2   = (const float*)d_in[4];
    const float* Wh1   = (const float*)d_in[5];
    const float* bh1   = (const float*)d_in[6];
    const float* wh2   = (const float*)d_in[7];
    const float* bh2   = (const float*)d_in[8];
    const float* Wf    = (const float*)d_in[9];
    const float* bf    = (const float*)d_in[10];
    const float* Wg    = (const float*)d_in[11];
    const float* bg    = (const float*)d_in[12];

    const int total = in_sizes[0] / 16;           // B*T rows
    const int threads = 256;
    const int blocks = (total + threads - 1) / threads;
    cbf_fused<<<blocks, threads>>>(state, Wc1, bc1, Wc2, bc2, Wh1, bh1, wh2, bh2,
                                   Wf, bf, Wg, bg, (float*)d_out, total);
}